// round 4
// baseline (speedup 1.0000x reference)
#include <cuda_runtime.h>

// Window attention: B=2, C=128, U=V=5, H=W=64, WS=8, SHIFT=4, heads=4, d=32
// One CTA per window (3200 windows), 256 threads, everything in smem.

#define NWIN 3200
#define SCALE_F 0.17677669529663689f   // 1/sqrt(32)

// smem layout (in floats)
#define XST_STRIDE 68      // Xst[128][68]  (k-major: [channel][token])
#define QKV_OFF    8704
#define QKV_STRIDE 392     // QKV[64][392]  ([token][h*96 + {q,k,v}])
#define WST_OFF    33792
#define WST_STRIDE 132     // Wst[128][132] (k-major weight tile [k][col])
#define RPB_OFF    50688   // rpb[225*4]
#define POUT_STRIDE 132    // Pout[64][132] reuses QKV region
#define SMEM_FLOATS 51588
#define SMEM_BYTES (SMEM_FLOATS * 4)

__global__ void __launch_bounds__(256, 1) win_attn_kernel(
    const float* __restrict__ x,
    const float* __restrict__ qkv_w,
    const float* __restrict__ qkv_b,
    const float* __restrict__ proj_w,
    const float* __restrict__ proj_b,
    const float* __restrict__ rpb_table,
    float* __restrict__ out)
{
    extern __shared__ float sm[];
    float* Xst = sm;                 // [128][68]
    float* QKV = sm + QKV_OFF;       // [64][392]
    float* Wst = sm + WST_OFF;       // [128][132]
    float* rpb = sm + RPB_OFF;       // [225*4]

    const int tid = threadIdx.x;
    const int w   = blockIdx.x;
    const int wn  = w & 7;
    const int hn  = (w >> 3) & 7;
    const int v   = (w / 64) % 5;
    const int u   = (w / 320) % 5;
    const int b   = w / 1600;

    // relative-position-bias table to smem (225 x 4 = 900 floats)
    for (int i = tid; i < 900; i += 256) rpb[i] = rpb_table[i];

    // base offset for (b, u, v); channel stride = U*V*H*W = 102400
    const int bbase = b * (128 * 102400) + (u * 5 + v) * 4096;
    const int h0 = hn * 8, w0 = wn * 8;

    // -------- Phase 1: gather shifted window into Xst[c][s] --------
    #pragma unroll
    for (int it = 0; it < 32; it++) {
        int idx = tid + it * 256;          // enumerate (c, s)
        int c = idx >> 6, s = idx & 63;
        int wv = s >> 3, wh = s & 7;
        int hg = (h0 + wv + 60) & 63;      // (h_s - SHIFT) mod 64
        int wg = (w0 + wh + 60) & 63;
        Xst[c * XST_STRIDE + s] = x[bbase + c * 102400 + hg * 64 + wg];
    }
    __syncthreads();

    const int rowg = tid >> 4;   // 0..15 : rows rowg*4 .. +3
    const int colg = tid & 15;   // 0..15 : cols colg + 16*j, j=0..7

    // -------- Phase 2: qkv GEMM, 3 passes of 128 output cols --------
    for (int p = 0; p < 3; p++) {
        #pragma unroll
        for (int it = 0; it < 64; it++) {
            int idx = tid + it * 256;
            int c = idx >> 7, k = idx & 127;
            Wst[k * WST_STRIDE + c] = qkv_w[(p * 128 + c) * 128 + k];
        }
        __syncthreads();

        float acc[4][8];
        #pragma unroll
        for (int j = 0; j < 8; j++) {
            float bv = qkv_b[p * 128 + colg + 16 * j];
            #pragma unroll
            for (int i = 0; i < 4; i++) acc[i][j] = bv;
        }
        #pragma unroll 4
        for (int k = 0; k < 128; k++) {
            float4 a = *(const float4*)&Xst[k * XST_STRIDE + rowg * 4];
            #pragma unroll
            for (int j = 0; j < 8; j++) {
                float bb = Wst[k * WST_STRIDE + colg + 16 * j];
                acc[0][j] += a.x * bb;
                acc[1][j] += a.y * bb;
                acc[2][j] += a.z * bb;
                acc[3][j] += a.w * bb;
            }
        }
        #pragma unroll
        for (int i = 0; i < 4; i++)
            #pragma unroll
            for (int j = 0; j < 8; j++)
                QKV[(rowg * 4 + i) * QKV_STRIDE + p * 128 + colg + 16 * j] = acc[i][j];
        __syncthreads();
    }

    // -------- Phase 3: attention (2 warps per head, thread = query row) --------
    {
        const int warp = tid >> 5, lane = tid & 31;
        const int h = warp >> 1;
        const int r = ((warp & 1) << 5) | lane;

        const float* qrow = &QKV[r * QKV_STRIDE + h * 96];
        float q[32];
        #pragma unroll
        for (int d4 = 0; d4 < 8; d4++) {
            float4 t = *(const float4*)&qrow[d4 * 4];
            q[d4 * 4 + 0] = t.x * SCALE_F;
            q[d4 * 4 + 1] = t.y * SCALE_F;
            q[d4 * 4 + 2] = t.z * SCALE_F;
            q[d4 * 4 + 3] = t.w * SCALE_F;
        }
        const int qi = r >> 3, qj = r & 7;
        const int bidx0 = (qi + 7) * 15 + (qj + 7);

        float sc[64];
        #pragma unroll
        for (int j = 0; j < 64; j++) {
            const float* krow = &QKV[j * QKV_STRIDE + h * 96 + 32];
            float a0 = 0.f, a1 = 0.f, a2 = 0.f, a3 = 0.f;
            #pragma unroll
            for (int d4 = 0; d4 < 8; d4++) {
                float4 t = *(const float4*)&krow[d4 * 4];
                a0 += q[d4 * 4 + 0] * t.x;
                a1 += q[d4 * 4 + 1] * t.y;
                a2 += q[d4 * 4 + 2] * t.z;
                a3 += q[d4 * 4 + 3] * t.w;
            }
            int ki = j >> 3, kj = j & 7;
            sc[j] = (a0 + a1) + (a2 + a3) + rpb[(bidx0 - ki * 15 - kj) * 4 + h];
        }

        float mx = -1e30f;
        #pragma unroll
        for (int j = 0; j < 64; j++) mx = fmaxf(mx, sc[j]);
        float sum = 0.f;
        #pragma unroll
        for (int j = 0; j < 64; j++) { sc[j] = __expf(sc[j] - mx); sum += sc[j]; }
        const float inv = 1.f / sum;

        float o[32];
        #pragma unroll
        for (int d = 0; d < 32; d++) o[d] = 0.f;
        #pragma unroll
        for (int j = 0; j < 64; j++) {
            const float* vrow = &QKV[j * QKV_STRIDE + h * 96 + 64];
            float pj = sc[j];
            #pragma unroll
            for (int d4 = 0; d4 < 8; d4++) {
                float4 t = *(const float4*)&vrow[d4 * 4];
                o[d4 * 4 + 0] += pj * t.x;
                o[d4 * 4 + 1] += pj * t.y;
                o[d4 * 4 + 2] += pj * t.z;
                o[d4 * 4 + 3] += pj * t.w;
            }
        }
        // write merged-head output channel-major into Xst (proj GEMM A operand)
        #pragma unroll
        for (int d = 0; d < 32; d++)
            Xst[(h * 32 + d) * XST_STRIDE + r] = o[d] * inv;
    }
    __syncthreads();

    // -------- Phase 4: proj GEMM (64x128 = Ost^T . proj_w^T) --------
    {
        #pragma unroll
        for (int it = 0; it < 64; it++) {
            int idx = tid + it * 256;
            int c = idx >> 7, k = idx & 127;
            Wst[k * WST_STRIDE + c] = proj_w[c * 128 + k];
        }
        __syncthreads();

        float acc[4][8];
        #pragma unroll
        for (int j = 0; j < 8; j++) {
            float bv = proj_b[colg + 16 * j];
            #pragma unroll
            for (int i = 0; i < 4; i++) acc[i][j] = bv;
        }
        #pragma unroll 4
        for (int k = 0; k < 128; k++) {
            float4 a = *(const float4*)&Xst[k * XST_STRIDE + rowg * 4];
            #pragma unroll
            for (int j = 0; j < 8; j++) {
                float bb = Wst[k * WST_STRIDE + colg + 16 * j];
                acc[0][j] += a.x * bb;
                acc[1][j] += a.y * bb;
                acc[2][j] += a.z * bb;
                acc[3][j] += a.w * bb;
            }
        }
        float* Pout = QKV;  // reuse, stride POUT_STRIDE
        #pragma unroll
        for (int i = 0; i < 4; i++)
            #pragma unroll
            for (int j = 0; j < 8; j++)
                Pout[(rowg * 4 + i) * POUT_STRIDE + colg + 16 * j] = acc[i][j];
    }
    __syncthreads();

    // -------- Phase 5: scatter with reverse shift --------
    {
        const float* Pout = QKV;
        #pragma unroll
        for (int it = 0; it < 32; it++) {
            int idx = tid + it * 256;
            int c = idx >> 6, s = idx & 63;
            int wv = s >> 3, wh = s & 7;
            int hg = (h0 + wv + 60) & 63;
            int wg = (w0 + wh + 60) & 63;
            out[bbase + c * 102400 + hg * 64 + wg] = Pout[s * POUT_STRIDE + c];
        }
    }
}

extern "C" void kernel_launch(void* const* d_in, const int* in_sizes, int n_in,
                              void* d_out, int out_size)
{
    const float* x      = (const float*)d_in[0];
    const float* qkv_w  = (const float*)d_in[1];
    const float* qkv_b  = (const float*)d_in[2];
    const float* proj_w = (const float*)d_in[3];
    const float* proj_b = (const float*)d_in[4];
    const float* rpb    = (const float*)d_in[5];
    float* out = (float*)d_out;

    cudaFuncSetAttribute(win_attn_kernel,
                         cudaFuncAttributeMaxDynamicSharedMemorySize, SMEM_BYTES);
    win_attn_kernel<<<NWIN, 256, SMEM_BYTES>>>(x, qkv_w, qkv_b, proj_w, proj_b, rpb, out);
}

// round 7
// speedup vs baseline: 1.6745x; 1.6745x over previous
#include <cuda_runtime.h>

// Shifted-window attention, fused per-window, tf32 mma.sync tensor cores.
// B=2, C=128, U=V=5, H=W=64, WS=8, SHIFT=4, heads=4, d=32. 3200 windows.
// One CTA per window, 256 threads (8 warps).
// QKV channel layout (matches reference reshape): head h -> q:96h..96h+31,
// k:96h+32..96h+63, v:96h+64..96h+95.

#define NWIN 3200
#define SCALE_F 0.17677669529663689f   // 1/sqrt(32)

// smem layout (in 32-bit words)
#define XS_OFF     0
#define XS_STRIDE  132      // Xs[64][132] token-major (tf32); later reused as Oa
#define QKV_OFF    8448
#define QKV_STRIDE 388      // QKV[64][388] (tf32), raw weight-column order
#define WST_OFF    33280
#define WST_STRIDE 136      // Wst[128][136] k-major weight tile (tf32)
#define PATT_OFF   33280    // Patt[4][64][68] overlaps Wst (disjoint lifetimes)
#define PATT_HEAD  4352
#define PATT_STRIDE 68
#define RPB_OFF    50688    // rpb[225*4] fp32
#define POUT_STRIDE 132     // Pout[64][132] fp32, reuses QKV region
#define SMEM_WORDS 51588
#define SMEM_BYTES (SMEM_WORDS * 4)

__device__ __forceinline__ unsigned int f2tf(float f) {
    unsigned int u;
    asm("cvt.rna.tf32.f32 %0, %1;" : "=r"(u) : "f"(f));
    return u;
}

__device__ __forceinline__ void mma_tf32(float d[4], const unsigned int a[4],
                                         const unsigned int b[2]) {
    asm("mma.sync.aligned.m16n8k8.row.col.f32.tf32.tf32.f32 "
        "{%0,%1,%2,%3}, {%4,%5,%6,%7}, {%8,%9}, {%0,%1,%2,%3};"
        : "+f"(d[0]), "+f"(d[1]), "+f"(d[2]), "+f"(d[3])
        : "r"(a[0]), "r"(a[1]), "r"(a[2]), "r"(a[3]), "r"(b[0]), "r"(b[1]));
}

__global__ void __launch_bounds__(256, 1) win_attn_kernel(
    const float* __restrict__ x,
    const float* __restrict__ qkv_w,
    const float* __restrict__ qkv_b,
    const float* __restrict__ proj_w,
    const float* __restrict__ proj_b,
    const float* __restrict__ rpb_table,
    float* __restrict__ out)
{
    extern __shared__ float sm[];
    unsigned int* smu = (unsigned int*)sm;
    float* rpb = sm + RPB_OFF;

    const int tid  = threadIdx.x;
    const int warp = tid >> 5, lane = tid & 31;
    const int g  = lane >> 2;     // groupID (row within fragment)
    const int tg = lane & 3;      // thread-in-group (k index)

    const int w  = blockIdx.x;
    const int wn = w & 7;
    const int hn = (w >> 3) & 7;
    const int v  = (w / 64) % 5;
    const int u  = (w / 320) % 5;
    const int b  = w / 1600;

    for (int i = tid; i < 900; i += 256) rpb[i] = rpb_table[i];

    const int bbase = b * (128 * 102400) + (u * 5 + v) * 4096;
    const int h0 = hn * 8, w0 = wn * 8;

    // ---- Phase 1: gather shifted window -> Xs[token][ch] (tf32) ----
    #pragma unroll
    for (int it = 0; it < 32; it++) {
        int idx = tid + it * 256;
        int c = idx >> 6, s = idx & 63;
        int wv = s >> 3, wh = s & 7;
        int hg = (h0 + wv + 60) & 63;
        int wg = (w0 + wh + 60) & 63;
        smu[XS_OFF + s * XS_STRIDE + c] = f2tf(x[bbase + c * 102400 + hg * 64 + wg]);
    }
    __syncthreads();

    // ---- Phase 2: qkv GEMM [64x128]x[128x384], 3 passes of N=128 ----
    {
        const int rb = warp & 3;      // 16-row block
        const int ch = warp >> 2;     // 64-col half
        const int arow = rb * 16 + g;

        for (int p = 0; p < 3; p++) {
            // stage W^T (k-major, tf32): Wst[k][c] = qkv_w[(p*128+c)*128 + k]
            {
                int c = tid >> 1, hf = tid & 1;
                const float4* src = (const float4*)&qkv_w[(p * 128 + c) * 128];
                #pragma unroll
                for (int j = 0; j < 16; j++) {
                    int k4 = hf * 16 + j;
                    float4 t = src[k4];
                    int kb = k4 * 4;
                    smu[WST_OFF + (kb + 0) * WST_STRIDE + c] = f2tf(t.x);
                    smu[WST_OFF + (kb + 1) * WST_STRIDE + c] = f2tf(t.y);
                    smu[WST_OFF + (kb + 2) * WST_STRIDE + c] = f2tf(t.z);
                    smu[WST_OFF + (kb + 3) * WST_STRIDE + c] = f2tf(t.w);
                }
            }
            __syncthreads();

            float acc[8][4];
            #pragma unroll
            for (int nt = 0; nt < 8; nt++)
                #pragma unroll
                for (int e = 0; e < 4; e++) acc[nt][e] = 0.f;

            #pragma unroll 4
            for (int k0 = 0; k0 < 128; k0 += 8) {
                unsigned int a[4];
                a[0] = smu[XS_OFF + arow * XS_STRIDE + k0 + tg];
                a[1] = smu[XS_OFF + (arow + 8) * XS_STRIDE + k0 + tg];
                a[2] = smu[XS_OFF + arow * XS_STRIDE + k0 + 4 + tg];
                a[3] = smu[XS_OFF + (arow + 8) * XS_STRIDE + k0 + 4 + tg];
                #pragma unroll
                for (int nt = 0; nt < 8; nt++) {
                    int n = ch * 64 + nt * 8 + g;
                    unsigned int bf[2];
                    bf[0] = smu[WST_OFF + (k0 + tg) * WST_STRIDE + n];
                    bf[1] = smu[WST_OFF + (k0 + 4 + tg) * WST_STRIDE + n];
                    mma_tf32(acc[nt], a, bf);
                }
            }

            // epilogue: +bias, write QKV as tf32 (no scaling here; folded into bias step)
            #pragma unroll
            for (int nt = 0; nt < 8; nt++) {
                int col0 = ch * 64 + nt * 8 + 2 * tg;
                float b0 = qkv_b[p * 128 + col0];
                float b1 = qkv_b[p * 128 + col0 + 1];
                int r0 = rb * 16 + g, r1 = r0 + 8;
                smu[QKV_OFF + r0 * QKV_STRIDE + p * 128 + col0]     = f2tf(acc[nt][0] + b0);
                smu[QKV_OFF + r0 * QKV_STRIDE + p * 128 + col0 + 1] = f2tf(acc[nt][1] + b1);
                smu[QKV_OFF + r1 * QKV_STRIDE + p * 128 + col0]     = f2tf(acc[nt][2] + b0);
                smu[QKV_OFF + r1 * QKV_STRIDE + p * 128 + col0 + 1] = f2tf(acc[nt][3] + b1);
            }
            __syncthreads();
        }
    }

    // ---- Phase 3: attention (2 warps per head, tensor cores) ----
    // head h channels: q at h*96, k at h*96+32, v at h*96+64
    {
        const int h = warp >> 1, half = warp & 1;
        const int rbase = half * 32;
        const int qoff = h * 96, koff = h * 96 + 32, voff = h * 96 + 64;
        unsigned int* Ph = smu + PATT_OFF + h * PATT_HEAD;

        // S = Q . K^T : M=32 (2 tiles), N=64 (8 tiles), K=32
        float S[2][8][4];
        #pragma unroll
        for (int mt = 0; mt < 2; mt++)
            #pragma unroll
            for (int nt = 0; nt < 8; nt++)
                #pragma unroll
                for (int e = 0; e < 4; e++) S[mt][nt][e] = 0.f;

        #pragma unroll
        for (int k0 = 0; k0 < 32; k0 += 8) {
            unsigned int a[2][4];
            #pragma unroll
            for (int mt = 0; mt < 2; mt++) {
                int r = rbase + mt * 16 + g;
                a[mt][0] = smu[QKV_OFF + r * QKV_STRIDE + qoff + k0 + tg];
                a[mt][1] = smu[QKV_OFF + (r + 8) * QKV_STRIDE + qoff + k0 + tg];
                a[mt][2] = smu[QKV_OFF + r * QKV_STRIDE + qoff + k0 + 4 + tg];
                a[mt][3] = smu[QKV_OFF + (r + 8) * QKV_STRIDE + qoff + k0 + 4 + tg];
            }
            #pragma unroll
            for (int nt = 0; nt < 8; nt++) {
                int n = nt * 8 + g;
                unsigned int bf[2];
                bf[0] = smu[QKV_OFF + n * QKV_STRIDE + koff + k0 + tg];
                bf[1] = smu[QKV_OFF + n * QKV_STRIDE + koff + k0 + 4 + tg];
                mma_tf32(S[0][nt], a[0], bf);
                mma_tf32(S[1][nt], a[1], bf);
            }
        }

        // scale + relative position bias, row max
        float mx[4] = {-1e30f, -1e30f, -1e30f, -1e30f};
        #pragma unroll
        for (int mt = 0; mt < 2; mt++)
            #pragma unroll
            for (int nt = 0; nt < 8; nt++)
                #pragma unroll
                for (int e = 0; e < 4; e++) {
                    int row = rbase + mt * 16 + g + ((e >> 1) << 3);
                    int col = nt * 8 + 2 * tg + (e & 1);
                    int qi = row >> 3, qj = row & 7, ki = col >> 3, kj = col & 7;
                    int bidx = (qi - ki + 7) * 15 + (qj - kj + 7);
                    float sv = S[mt][nt][e] * SCALE_F + rpb[bidx * 4 + h];
                    S[mt][nt][e] = sv;
                    int slot = mt * 2 + (e >> 1);
                    mx[slot] = fmaxf(mx[slot], sv);
                }
        #pragma unroll
        for (int s4 = 0; s4 < 4; s4++) {
            mx[s4] = fmaxf(mx[s4], __shfl_xor_sync(0xffffffffu, mx[s4], 1));
            mx[s4] = fmaxf(mx[s4], __shfl_xor_sync(0xffffffffu, mx[s4], 2));
        }

        // exp + row sums
        float sum[4] = {0.f, 0.f, 0.f, 0.f};
        #pragma unroll
        for (int mt = 0; mt < 2; mt++)
            #pragma unroll
            for (int nt = 0; nt < 8; nt++)
                #pragma unroll
                for (int e = 0; e < 4; e++) {
                    int slot = mt * 2 + (e >> 1);
                    float ev = __expf(S[mt][nt][e] - mx[slot]);
                    S[mt][nt][e] = ev;
                    sum[slot] += ev;
                }
        #pragma unroll
        for (int s4 = 0; s4 < 4; s4++) {
            sum[s4] += __shfl_xor_sync(0xffffffffu, sum[s4], 1);
            sum[s4] += __shfl_xor_sync(0xffffffffu, sum[s4], 2);
        }
        float inv[4];
        #pragma unroll
        for (int s4 = 0; s4 < 4; s4++) inv[s4] = 1.f / sum[s4];

        // write unnormalized P (tf32) to this warp's own rows
        #pragma unroll
        for (int mt = 0; mt < 2; mt++)
            #pragma unroll
            for (int nt = 0; nt < 8; nt++)
                #pragma unroll
                for (int e = 0; e < 4; e++) {
                    int row = rbase + mt * 16 + g + ((e >> 1) << 3);
                    int col = nt * 8 + 2 * tg + (e & 1);
                    Ph[row * PATT_STRIDE + col] = f2tf(S[mt][nt][e]);
                }
        __syncwarp();

        // O = P . V : M=32, N=32 (4 tiles), K=64
        float O[2][4][4];
        #pragma unroll
        for (int mt = 0; mt < 2; mt++)
            #pragma unroll
            for (int nt = 0; nt < 4; nt++)
                #pragma unroll
                for (int e = 0; e < 4; e++) O[mt][nt][e] = 0.f;

        #pragma unroll
        for (int k0 = 0; k0 < 64; k0 += 8) {
            unsigned int a[2][4];
            #pragma unroll
            for (int mt = 0; mt < 2; mt++) {
                int r = rbase + mt * 16 + g;
                a[mt][0] = Ph[r * PATT_STRIDE + k0 + tg];
                a[mt][1] = Ph[(r + 8) * PATT_STRIDE + k0 + tg];
                a[mt][2] = Ph[r * PATT_STRIDE + k0 + 4 + tg];
                a[mt][3] = Ph[(r + 8) * PATT_STRIDE + k0 + 4 + tg];
            }
            #pragma unroll
            for (int nt = 0; nt < 4; nt++) {
                int n = nt * 8 + g;
                unsigned int bf[2];
                bf[0] = smu[QKV_OFF + (k0 + tg) * QKV_STRIDE + voff + n];
                bf[1] = smu[QKV_OFF + (k0 + 4 + tg) * QKV_STRIDE + voff + n];
                mma_tf32(O[0][nt], a[0], bf);
                mma_tf32(O[1][nt], a[1], bf);
            }
        }

        // normalize and write merged-head output (tf32) into Xs region (Oa)
        #pragma unroll
        for (int mt = 0; mt < 2; mt++)
            #pragma unroll
            for (int nt = 0; nt < 4; nt++)
                #pragma unroll
                for (int e = 0; e < 4; e++) {
                    int row = rbase + mt * 16 + g + ((e >> 1) << 3);
                    int col = nt * 8 + 2 * tg + (e & 1);
                    int slot = mt * 2 + (e >> 1);
                    smu[XS_OFF + row * XS_STRIDE + 32 * h + col] =
                        f2tf(O[mt][nt][e] * inv[slot]);
                }
    }
    __syncthreads();

    // ---- Phase 4: proj GEMM [64x128]x[128x128] ----
    {
        // stage proj weights (overwrites Patt region)
        {
            int c = tid >> 1, hf = tid & 1;
            const float4* src = (const float4*)&proj_w[c * 128];
            #pragma unroll
            for (int j = 0; j < 16; j++) {
                int k4 = hf * 16 + j;
                float4 t = src[k4];
                int kb = k4 * 4;
                smu[WST_OFF + (kb + 0) * WST_STRIDE + c] = f2tf(t.x);
                smu[WST_OFF + (kb + 1) * WST_STRIDE + c] = f2tf(t.y);
                smu[WST_OFF + (kb + 2) * WST_STRIDE + c] = f2tf(t.z);
                smu[WST_OFF + (kb + 3) * WST_STRIDE + c] = f2tf(t.w);
            }
        }
        __syncthreads();

        const int rb = warp & 3;
        const int ch = warp >> 2;
        const int arow = rb * 16 + g;

        float acc[8][4];
        #pragma unroll
        for (int nt = 0; nt < 8; nt++)
            #pragma unroll
            for (int e = 0; e < 4; e++) acc[nt][e] = 0.f;

        #pragma unroll 4
        for (int k0 = 0; k0 < 128; k0 += 8) {
            unsigned int a[4];
            a[0] = smu[XS_OFF + arow * XS_STRIDE + k0 + tg];
            a[1] = smu[XS_OFF + (arow + 8) * XS_STRIDE + k0 + tg];
            a[2] = smu[XS_OFF + arow * XS_STRIDE + k0 + 4 + tg];
            a[3] = smu[XS_OFF + (arow + 8) * XS_STRIDE + k0 + 4 + tg];
            #pragma unroll
            for (int nt = 0; nt < 8; nt++) {
                int n = ch * 64 + nt * 8 + g;
                unsigned int bf[2];
                bf[0] = smu[WST_OFF + (k0 + tg) * WST_STRIDE + n];
                bf[1] = smu[WST_OFF + (k0 + 4 + tg) * WST_STRIDE + n];
                mma_tf32(acc[nt], a, bf);
            }
        }

        // epilogue: +bias, write fp32 Pout into QKV region
        #pragma unroll
        for (int nt = 0; nt < 8; nt++) {
            int col0 = ch * 64 + nt * 8 + 2 * tg;
            float b0 = proj_b[col0], b1 = proj_b[col0 + 1];
            int r0 = rb * 16 + g, r1 = r0 + 8;
            sm[QKV_OFF + r0 * POUT_STRIDE + col0]     = acc[nt][0] + b0;
            sm[QKV_OFF + r0 * POUT_STRIDE + col0 + 1] = acc[nt][1] + b1;
            sm[QKV_OFF + r1 * POUT_STRIDE + col0]     = acc[nt][2] + b0;
            sm[QKV_OFF + r1 * POUT_STRIDE + col0 + 1] = acc[nt][3] + b1;
        }
    }
    __syncthreads();

    // ---- Phase 5: scatter with reverse shift ----
    #pragma unroll
    for (int it = 0; it < 32; it++) {
        int idx = tid + it * 256;
        int c = idx >> 6, s = idx & 63;
        int wv = s >> 3, wh = s & 7;
        int hg = (h0 + wv + 60) & 63;
        int wg = (w0 + wh + 60) & 63;
        out[bbase + c * 102400 + hg * 64 + wg] = sm[QKV_OFF + s * POUT_STRIDE + c];
    }
}

extern "C" void kernel_launch(void* const* d_in, const int* in_sizes, int n_in,
                              void* d_out, int out_size)
{
    const float* x      = (const float*)d_in[0];
    const float* qkv_w  = (const float*)d_in[1];
    const float* qkv_b  = (const float*)d_in[2];
    const float* proj_w = (const float*)d_in[3];
    const float* proj_b = (const float*)d_in[4];
    const float* rpb    = (const float*)d_in[5];
    float* out = (float*)d_out;

    cudaFuncSetAttribute(win_attn_kernel,
                         cudaFuncAttributeMaxDynamicSharedMemorySize, SMEM_BYTES);
    win_attn_kernel<<<NWIN, 256, SMEM_BYTES>>>(x, qkv_w, qkv_b, proj_w, proj_b, rpb, out);
}

// round 10
// speedup vs baseline: 2.4408x; 1.4576x over previous
#include <cuda_runtime.h>
#include <cuda_fp16.h>

// Shifted-window attention, fused per-window, fp16 mma.sync (m16n8k16) + ldmatrix.
// B=2, C=128, U=V=5, H=W=64, WS=8, SHIFT=4, heads=4, d=32. 3200 windows.
// One CTA per window, 256 threads (8 warps), 2 CTAs/SM.
// QKV channel layout (reference reshape): head h -> q:96h.. , k:96h+32.., v:96h+64..

#define NWIN 3200
#define SCALE_F 0.17677669529663689f

// smem layout, byte offsets. All strides chosen so stride_bytes mod 128 == 16
// (conflict-free ldmatrix row addressing within each 8-lane phase).
#define XS_OFF      0          // Xs[64][136] halves (tokens x channels); later Oa
#define XS_STRIDE   136
#define QKV_OFF     17408      // QKV[64][392] halves
#define QKV_STRIDE  392
#define WST_OFF     67584      // Wst[128][136] halves (weights [out][in])
#define WST_STRIDE  136
#define P_OFF       67584      // P[4][64][72] halves, overlaps Wst
#define P_HEAD      9216       // bytes per head
#define P_STRIDE    72
#define RPB_OFF     104448     // rpb[900] fp32
#define POUT_OFF    17408      // Pout[64][132] fp32, reuses QKV
#define POUT_STRIDE 132
#define SMEM_BYTES  108048

__device__ __forceinline__ unsigned int smem_u32(const void* p) {
    unsigned int a;
    asm("{ .reg .u64 t; cvta.to.shared.u64 t, %1; cvt.u32.u64 %0, t; }"
        : "=r"(a) : "l"(p));
    return a;
}

__device__ __forceinline__ void ldsm_x4(unsigned int r[4], unsigned int addr) {
    asm volatile("ldmatrix.sync.aligned.m8n8.x4.shared.b16 {%0,%1,%2,%3}, [%4];"
                 : "=r"(r[0]), "=r"(r[1]), "=r"(r[2]), "=r"(r[3]) : "r"(addr));
}
__device__ __forceinline__ void ldsm_x2(unsigned int r[2], unsigned int addr) {
    asm volatile("ldmatrix.sync.aligned.m8n8.x2.shared.b16 {%0,%1}, [%2];"
                 : "=r"(r[0]), "=r"(r[1]) : "r"(addr));
}
__device__ __forceinline__ void ldsm_x2t(unsigned int r[2], unsigned int addr) {
    asm volatile("ldmatrix.sync.aligned.m8n8.x2.trans.shared.b16 {%0,%1}, [%2];"
                 : "=r"(r[0]), "=r"(r[1]) : "r"(addr));
}
__device__ __forceinline__ void mma_f16(float d[4], const unsigned int a[4],
                                        const unsigned int b[2]) {
    asm volatile("mma.sync.aligned.m16n8k16.row.col.f32.f16.f16.f32 "
                 "{%0,%1,%2,%3},{%4,%5,%6,%7},{%8,%9},{%0,%1,%2,%3};"
                 : "+f"(d[0]), "+f"(d[1]), "+f"(d[2]), "+f"(d[3])
                 : "r"(a[0]), "r"(a[1]), "r"(a[2]), "r"(a[3]),
                   "r"(b[0]), "r"(b[1]));
}

// stage a [128][128] fp32 weight matrix (row-major [out][in]) into Wst fp16
__device__ __forceinline__ void stage_weights(char* smc, const float* __restrict__ wsrc,
                                              int tid) {
    int c = tid >> 1, hf = tid & 1;
    const float4* src = (const float4*)&wsrc[c * 128];
    __half2* dst = (__half2*)((__half*)(smc + WST_OFF) + c * WST_STRIDE + hf * 64);
    #pragma unroll
    for (int j = 0; j < 8; j++) {
        float4 t0 = src[hf * 16 + 2 * j];
        float4 t1 = src[hf * 16 + 2 * j + 1];
        dst[j * 4 + 0] = __floats2half2_rn(t0.x, t0.y);
        dst[j * 4 + 1] = __floats2half2_rn(t0.z, t0.w);
        dst[j * 4 + 2] = __floats2half2_rn(t1.x, t1.y);
        dst[j * 4 + 3] = __floats2half2_rn(t1.z, t1.w);
    }
}

__global__ void __launch_bounds__(256, 2) win_attn_kernel(
    const float* __restrict__ x,
    const float* __restrict__ qkv_w,
    const float* __restrict__ qkv_b,
    const float* __restrict__ proj_w,
    const float* __restrict__ proj_b,
    const float* __restrict__ rpb_table,
    float* __restrict__ out)
{
    extern __shared__ char smc[];
    const unsigned int smb = smem_u32(smc);
    float* rpb  = (float*)(smc + RPB_OFF);

    const int tid  = threadIdx.x;
    const int warp = tid >> 5, lane = tid & 31;
    const int g  = lane >> 2;
    const int tg = lane & 3;
    const int lq = lane & 15;          // ldmatrix quad-row index

    const int w  = blockIdx.x;
    const int wn = w & 7;
    const int hn = (w >> 3) & 7;
    const int v  = (w / 64) % 5;
    const int u  = (w / 320) % 5;
    const int b  = w / 1600;

    for (int i = tid; i < 900; i += 256) rpb[i] = rpb_table[i];

    const int bbase = b * (128 * 102400) + (u * 5 + v) * 4096;
    const int h0 = hn * 8, w0 = wn * 8;

    // ---- Phase 1: gather shifted window -> Xs[token][ch] fp16 ----
    {
        __half2* xs2 = (__half2*)(smc + XS_OFF);
        #pragma unroll
        for (int it = 0; it < 16; it++) {
            int idx = tid + it * 256;          // 64 s x 64 channel-pairs
            int s = idx & 63, cp = idx >> 6;
            int wv = s >> 3, wh = s & 7;
            int hg = (h0 + wv + 60) & 63;
            int wg = (w0 + wh + 60) & 63;
            float v0 = x[bbase + (2 * cp)     * 102400 + hg * 64 + wg];
            float v1 = x[bbase + (2 * cp + 1) * 102400 + hg * 64 + wg];
            xs2[(s * XS_STRIDE) / 2 + cp] = __floats2half2_rn(v0, v1);
        }
    }
    __syncthreads();

    const int m0 = (warp >> 2) * 32;   // 0 or 32
    const int n0 = (warp & 3) * 32;    // 0,32,64,96

    // per-thread ldmatrix address components (in halves; *2 at use site)
    const int aRow = lq;                         // + m-base
    const int aCol = (lane >> 4) << 3;           // 0 or 8, + k0
    const int bRow = lq & 7;                     // + n-base
    const int bCol = (lq >> 3) << 3;             // 0 or 8, + k0

    // ---- Phase 2: qkv GEMM [64x128]x[128x384]^T, 3 passes ----
    for (int p = 0; p < 3; p++) {
        stage_weights(smc, qkv_w + p * 128 * 128, tid);
        __syncthreads();

        float acc[2][4][4];
        #pragma unroll
        for (int mt = 0; mt < 2; mt++)
            #pragma unroll
            for (int nt = 0; nt < 4; nt++)
                #pragma unroll
                for (int e = 0; e < 4; e++) acc[mt][nt][e] = 0.f;

        #pragma unroll 4
        for (int k0 = 0; k0 < 128; k0 += 16) {
            unsigned int a[2][4];
            #pragma unroll
            for (int mt = 0; mt < 2; mt++)
                ldsm_x4(a[mt], smb + XS_OFF +
                        (((m0 + mt * 16 + aRow) * XS_STRIDE) + k0 + aCol) * 2);
            #pragma unroll
            for (int nt = 0; nt < 4; nt++) {
                unsigned int bf[2];
                ldsm_x2(bf, smb + WST_OFF +
                        (((n0 + nt * 8 + bRow) * WST_STRIDE) + k0 + bCol) * 2);
                mma_f16(acc[0][nt], a[0], bf);
                mma_f16(acc[1][nt], a[1], bf);
            }
        }

        // epilogue: +bias, fp16 half2 stores (conflict-free: bank = 4g+tg)
        __half2* qkv2 = (__half2*)(smc + QKV_OFF);
        #pragma unroll
        for (int mt = 0; mt < 2; mt++)
            #pragma unroll
            for (int nt = 0; nt < 4; nt++) {
                int col0 = n0 + nt * 8 + 2 * tg;
                float b0 = qkv_b[p * 128 + col0];
                float b1 = qkv_b[p * 128 + col0 + 1];
                int r0 = m0 + mt * 16 + g, r1 = r0 + 8;
                int cofs = (p * 128 + col0) >> 1;
                qkv2[(r0 * QKV_STRIDE) / 2 + cofs] =
                    __floats2half2_rn(acc[mt][nt][0] + b0, acc[mt][nt][1] + b1);
                qkv2[(r1 * QKV_STRIDE) / 2 + cofs] =
                    __floats2half2_rn(acc[mt][nt][2] + b0, acc[mt][nt][3] + b1);
            }
        __syncthreads();
    }

    // ---- Phase 3: attention, 2 warps/head ----
    {
        const int h = warp >> 1, hw = warp & 1;
        const int rbase = hw * 32;
        const int qcol = h * 96, kcol = qcol + 32, vcol = qcol + 64;
        const unsigned int Pb = smb + P_OFF + h * P_HEAD;

        // S = Q.K^T : M=32, N=64 (8 nt), K=32 (2 ksteps)
        float S[2][8][4];
        #pragma unroll
        for (int mt = 0; mt < 2; mt++)
            #pragma unroll
            for (int nt = 0; nt < 8; nt++)
                #pragma unroll
                for (int e = 0; e < 4; e++) S[mt][nt][e] = 0.f;

        #pragma unroll
        for (int k0 = 0; k0 < 32; k0 += 16) {
            unsigned int a[2][4];
            #pragma unroll
            for (int mt = 0; mt < 2; mt++)
                ldsm_x4(a[mt], smb + QKV_OFF +
                        (((rbase + mt * 16 + aRow) * QKV_STRIDE) + qcol + k0 + aCol) * 2);
            #pragma unroll
            for (int nt = 0; nt < 8; nt++) {
                unsigned int bf[2];
                ldsm_x2(bf, smb + QKV_OFF +
                        (((nt * 8 + bRow) * QKV_STRIDE) + kcol + k0 + bCol) * 2);
                mma_f16(S[0][nt], a[0], bf);
                mma_f16(S[1][nt], a[1], bf);
            }
        }

        // scale + bias, softmax (row-local + 4-lane shfl reduce)
        float mx[4] = {-1e30f, -1e30f, -1e30f, -1e30f};
        #pragma unroll
        for (int mt = 0; mt < 2; mt++)
            #pragma unroll
            for (int nt = 0; nt < 8; nt++)
                #pragma unroll
                for (int e = 0; e < 4; e++) {
                    int row = rbase + mt * 16 + g + ((e >> 1) << 3);
                    int col = nt * 8 + 2 * tg + (e & 1);
                    int qi = row >> 3, qj = row & 7, ki = col >> 3, kj = col & 7;
                    int bidx = (qi - ki + 7) * 15 + (qj - kj + 7);
                    float sv = S[mt][nt][e] * SCALE_F + rpb[bidx * 4 + h];
                    S[mt][nt][e] = sv;
                    int slot = mt * 2 + (e >> 1);
                    mx[slot] = fmaxf(mx[slot], sv);
                }
        #pragma unroll
        for (int s4 = 0; s4 < 4; s4++) {
            mx[s4] = fmaxf(mx[s4], __shfl_xor_sync(0xffffffffu, mx[s4], 1));
            mx[s4] = fmaxf(mx[s4], __shfl_xor_sync(0xffffffffu, mx[s4], 2));
        }
        float sum[4] = {0.f, 0.f, 0.f, 0.f};
        #pragma unroll
        for (int mt = 0; mt < 2; mt++)
            #pragma unroll
            for (int nt = 0; nt < 8; nt++)
                #pragma unroll
                for (int e = 0; e < 4; e++) {
                    int slot = mt * 2 + (e >> 1);
                    float ev = __expf(S[mt][nt][e] - mx[slot]);
                    S[mt][nt][e] = ev;
                    sum[slot] += ev;
                }
        #pragma unroll
        for (int s4 = 0; s4 < 4; s4++) {
            sum[s4] += __shfl_xor_sync(0xffffffffu, sum[s4], 1);
            sum[s4] += __shfl_xor_sync(0xffffffffu, sum[s4], 2);
        }
        float inv[4];
        #pragma unroll
        for (int s4 = 0; s4 < 4; s4++) inv[s4] = 1.f / sum[s4];

        // store unnormalized P fp16 (own rows only)
        {
            __half2* P2 = (__half2*)(smc + P_OFF + h * P_HEAD);
            #pragma unroll
            for (int mt = 0; mt < 2; mt++)
                #pragma unroll
                for (int nt = 0; nt < 8; nt++) {
                    int col0 = nt * 8 + 2 * tg;
                    int r0 = rbase + mt * 16 + g, r1 = r0 + 8;
                    P2[(r0 * P_STRIDE + col0) / 2] =
                        __floats2half2_rn(S[mt][nt][0], S[mt][nt][1]);
                    P2[(r1 * P_STRIDE + col0) / 2] =
                        __floats2half2_rn(S[mt][nt][2], S[mt][nt][3]);
                }
        }
        __syncwarp();

        // O = P.V : M=32, N=32 (4 nt), K=64 (4 ksteps). V via ldmatrix.trans.
        float O[2][4][4];
        #pragma unroll
        for (int mt = 0; mt < 2; mt++)
            #pragma unroll
            for (int nt = 0; nt < 4; nt++)
                #pragma unroll
                for (int e = 0; e < 4; e++) O[mt][nt][e] = 0.f;

        #pragma unroll
        for (int k0 = 0; k0 < 64; k0 += 16) {
            unsigned int a[2][4];
            #pragma unroll
            for (int mt = 0; mt < 2; mt++)
                ldsm_x4(a[mt], Pb +
                        (((rbase + mt * 16 + aRow) * P_STRIDE) + k0 + aCol) * 2);
            #pragma unroll
            for (int nt = 0; nt < 4; nt++) {
                unsigned int bf[2];
                ldsm_x2t(bf, smb + QKV_OFF +
                         (((k0 + lq) * QKV_STRIDE) + vcol + nt * 8) * 2);
                mma_f16(O[0][nt], a[0], bf);
                mma_f16(O[1][nt], a[1], bf);
            }
        }

        // normalize, write merged-head Oa fp16 into Xs region
        {
            __half2* oa2 = (__half2*)(smc + XS_OFF);
            #pragma unroll
            for (int mt = 0; mt < 2; mt++)
                #pragma unroll
                for (int nt = 0; nt < 4; nt++) {
                    int col0 = h * 32 + nt * 8 + 2 * tg;
                    int r0 = rbase + mt * 16 + g, r1 = r0 + 8;
                    int slot0 = mt * 2, slot1 = mt * 2 + 1;
                    oa2[(r0 * XS_STRIDE + col0) / 2] = __floats2half2_rn(
                        O[mt][nt][0] * inv[slot0], O[mt][nt][1] * inv[slot0]);
                    oa2[(r1 * XS_STRIDE + col0) / 2] = __floats2half2_rn(
                        O[mt][nt][2] * inv[slot1], O[mt][nt][3] * inv[slot1]);
                }
        }
    }
    __syncthreads();

    // ---- Phase 4: proj GEMM [64x128]x[128x128]^T ----
    {
        stage_weights(smc, proj_w, tid);   // overwrites P region
        __syncthreads();

        float acc[2][4][4];
        #pragma unroll
        for (int mt = 0; mt < 2; mt++)
            #pragma unroll
            for (int nt = 0; nt < 4; nt++)
                #pragma unroll
                for (int e = 0; e < 4; e++) acc[mt][nt][e] = 0.f;

        #pragma unroll 4
        for (int k0 = 0; k0 < 128; k0 += 16) {
            unsigned int a[2][4];
            #pragma unroll
            for (int mt = 0; mt < 2; mt++)
                ldsm_x4(a[mt], smb + XS_OFF +
                        (((m0 + mt * 16 + aRow) * XS_STRIDE) + k0 + aCol) * 2);
            #pragma unroll
            for (int nt = 0; nt < 4; nt++) {
                unsigned int bf[2];
                ldsm_x2(bf, smb + WST_OFF +
                        (((n0 + nt * 8 + bRow) * WST_STRIDE) + k0 + bCol) * 2);
                mma_f16(acc[0][nt], a[0], bf);
                mma_f16(acc[1][nt], a[1], bf);
            }
        }

        // epilogue: +bias, fp32 store to Pout (QKV region reused)
        float* Pout = (float*)(smc + POUT_OFF);
        #pragma unroll
        for (int mt = 0; mt < 2; mt++)
            #pragma unroll
            for (int nt = 0; nt < 4; nt++) {
                int col0 = n0 + nt * 8 + 2 * tg;
                float b0 = proj_b[col0], b1 = proj_b[col0 + 1];
                int r0 = m0 + mt * 16 + g, r1 = r0 + 8;
                Pout[r0 * POUT_STRIDE + col0]     = acc[mt][nt][0] + b0;
                Pout[r0 * POUT_STRIDE + col0 + 1] = acc[mt][nt][1] + b1;
                Pout[r1 * POUT_STRIDE + col0]     = acc[mt][nt][2] + b0;
                Pout[r1 * POUT_STRIDE + col0 + 1] = acc[mt][nt][3] + b1;
            }
    }
    __syncthreads();

    // ---- Phase 5: scatter with reverse shift ----
    {
        const float* Pout = (const float*)(smc + POUT_OFF);
        #pragma unroll
        for (int it = 0; it < 32; it++) {
            int idx = tid + it * 256;
            int c = idx >> 6, s = idx & 63;
            int wv = s >> 3, wh = s & 7;
            int hg = (h0 + wv + 60) & 63;
            int wg = (w0 + wh + 60) & 63;
            out[bbase + c * 102400 + hg * 64 + wg] = Pout[s * POUT_STRIDE + c];
        }
    }
}

extern "C" void kernel_launch(void* const* d_in, const int* in_sizes, int n_in,
                              void* d_out, int out_size)
{
    const float* x      = (const float*)d_in[0];
    const float* qkv_w  = (const float*)d_in[1];
    const float* qkv_b  = (const float*)d_in[2];
    const float* proj_w = (const float*)d_in[3];
    const float* proj_b = (const float*)d_in[4];
    const float* rpb    = (const float*)d_in[5];
    float* out = (float*)d_out;

    cudaFuncSetAttribute(win_attn_kernel,
                         cudaFuncAttributeMaxDynamicSharedMemorySize, SMEM_BYTES);
    win_attn_kernel<<<NWIN, 256, SMEM_BYTES>>>(x, qkv_w, qkv_b, proj_w, proj_b, rpb, out);
}

// round 14
// speedup vs baseline: 4.2765x; 1.7521x over previous
#include <cuda_runtime.h>
#include <cuda_fp16.h>

// Shifted-window attention, fused per-window, fp16 mma.sync + ldmatrix.
// B=2, C=128, U=V=5, H=W=64, WS=8, SHIFT=4, heads=4, d=32. 3200 windows.
// One CTA per window, 256 threads (8 warps), 2 CTAs/SM.
// P (attention probs) kept entirely in registers (S-frag == PV A-frag).

#define NWIN 3200
#define SCALE_F 0.17677669529663689f

// smem layout (byte offsets). Word-strides chosen != 0 mod 8 words for
// conflict-free ldmatrix phases.
#define XST_OFF    0        // gather: channel-major [128][72] halves
#define XST_STRIDE 72
#define OA_STRIDE  136      // attention out, token-major [64][136] halves (overlays XST)
#define QKV_OFF    18432    // [64][392] halves
#define QKV_STRIDE 392
#define WST_OFF    68608    // [128][136] halves, weights [out][in]
#define WST_STRIDE 136
#define RPB_OFF    103424   // 900 fp32
#define POUT_OFF   18432    // fp32 [64][132], overlays QKV
#define POUT_STRIDE 132
#define SMEM_BYTES 107024

__device__ __forceinline__ unsigned int smem_u32(const void* p) {
    unsigned int a;
    asm("{ .reg .u64 t; cvta.to.shared.u64 t, %1; cvt.u32.u64 %0, t; }"
        : "=r"(a) : "l"(p));
    return a;
}
__device__ __forceinline__ void ldsm_x4(unsigned int r[4], unsigned int addr) {
    asm volatile("ldmatrix.sync.aligned.m8n8.x4.shared.b16 {%0,%1,%2,%3}, [%4];"
                 : "=r"(r[0]), "=r"(r[1]), "=r"(r[2]), "=r"(r[3]) : "r"(addr));
}
__device__ __forceinline__ void ldsm_x4t(unsigned int r[4], unsigned int addr) {
    asm volatile("ldmatrix.sync.aligned.m8n8.x4.trans.shared.b16 {%0,%1,%2,%3}, [%4];"
                 : "=r"(r[0]), "=r"(r[1]), "=r"(r[2]), "=r"(r[3]) : "r"(addr));
}
__device__ __forceinline__ void mma_f16(float d[4], const unsigned int a[4],
                                        unsigned int b0, unsigned int b1) {
    asm volatile("mma.sync.aligned.m16n8k16.row.col.f32.f16.f16.f32 "
                 "{%0,%1,%2,%3},{%4,%5,%6,%7},{%8,%9},{%0,%1,%2,%3};"
                 : "+f"(d[0]), "+f"(d[1]), "+f"(d[2]), "+f"(d[3])
                 : "r"(a[0]), "r"(a[1]), "r"(a[2]), "r"(a[3]), "r"(b0), "r"(b1));
}
__device__ __forceinline__ unsigned int pack2(float a, float b) {
    __half2 h = __floats2half2_rn(a, b);
    return *(unsigned int*)&h;
}

// Coalesced weight staging: [128][128] fp32 row-major -> Wst fp16 [out][in].
// Warp j-iter reads ONE contiguous 512B row (4 lines/LDG.128), stores STS.64
// conflict-free (banks 2*lane).
__device__ __forceinline__ void stage_weights(char* smc, const float* __restrict__ wsrc,
                                              int warp, int lane) {
    __half* wst = (__half*)(smc + WST_OFF);
    #pragma unroll
    for (int j = 0; j < 16; j++) {
        int c = warp + 8 * j;
        float4 t = *(const float4*)&wsrc[c * 128 + lane * 4];
        __half2 h0 = __floats2half2_rn(t.x, t.y);
        __half2 h1 = __floats2half2_rn(t.z, t.w);
        uint2 pkt = make_uint2(*(unsigned int*)&h0, *(unsigned int*)&h1);
        *(uint2*)(wst + c * WST_STRIDE + lane * 4) = pkt;
    }
}

__global__ void __launch_bounds__(256, 2) win_attn_kernel(
    const float* __restrict__ x,
    const float* __restrict__ qkv_w,
    const float* __restrict__ qkv_b,
    const float* __restrict__ proj_w,
    const float* __restrict__ proj_b,
    const float* __restrict__ rpb_table,
    float* __restrict__ out)
{
    extern __shared__ char smc[];
    const unsigned int smb = smem_u32(smc);
    float* rpb = (float*)(smc + RPB_OFF);

    const int tid  = threadIdx.x;
    const int warp = tid >> 5, lane = tid & 31;
    const int g  = lane >> 2;
    const int tg = lane & 3;
    const int lq = lane & 15;
    const int hi8 = (lane >> 4) << 3;     // 0 or 8 (k half)

    const int w  = blockIdx.x;
    const int wn = w & 7;
    const int hn = (w >> 3) & 7;
    const int v  = (w / 64) % 5;
    const int u  = (w / 320) % 5;
    const int b  = w / 1600;

    for (int i = tid; i < 900; i += 256) rpb[i] = rpb_table[i];

    const int bbase = b * (128 * 102400) + (u * 5 + v) * 4096;
    const int h0 = hn * 8, w0 = wn * 8;

    // ---- Phase 1: gather (vectorized) -> Xst[channel][token] fp16 ----
    {
        __half* xst = (__half*)(smc + XST_OFF);
        #pragma unroll
        for (int it = 0; it < 8; it++) {
            int idx = tid + it * 256;       // 2048 = 128 c x 16 (row,half)
            int rh = idx & 15, c = idx >> 4;
            int wv = rh >> 1, hf = rh & 1;
            int hg = (h0 + wv + 60) & 63;
            int wg = (w0 + hf * 4 + 60) & 63;   // 16B aligned, no wrap inside 4
            float4 t = *(const float4*)&x[bbase + c * 102400 + hg * 64 + wg];
            __half2 h0p = __floats2half2_rn(t.x, t.y);
            __half2 h1p = __floats2half2_rn(t.z, t.w);
            uint2 pkt = make_uint2(*(unsigned int*)&h0p, *(unsigned int*)&h1p);
            *(uint2*)(xst + c * XST_STRIDE + wv * 8 + hf * 4) = pkt;
        }
    }
    __syncthreads();

    const int m0 = (warp >> 2) * 32;   // 0 or 32
    const int n0 = (warp & 3) * 32;    // 0,32,64,96

    // trans-A lane addressing (A stored k-major [c][token])
    const int tKrow = (lane & 7) + hi8;
    const int tMcol = lane & 8;

    // ---- Phase 2: qkv GEMM [64x128]x[128x384]^T, 3 passes ----
    for (int p = 0; p < 3; p++) {
        stage_weights(smc, qkv_w + p * 128 * 128, warp, lane);
        __syncthreads();

        float acc[2][4][4];
        #pragma unroll
        for (int mt = 0; mt < 2; mt++)
            #pragma unroll
            for (int nt = 0; nt < 4; nt++)
                #pragma unroll
                for (int e = 0; e < 4; e++) acc[mt][nt][e] = 0.f;

        #pragma unroll 4
        for (int k0 = 0; k0 < 128; k0 += 16) {
            unsigned int a[2][4];
            #pragma unroll
            for (int mt = 0; mt < 2; mt++)
                ldsm_x4t(a[mt], smb + XST_OFF +
                         (((k0 + tKrow) * XST_STRIDE) + m0 + mt * 16 + tMcol) * 2);
            #pragma unroll
            for (int ntp = 0; ntp < 2; ntp++) {
                unsigned int bf[4];
                ldsm_x4(bf, smb + WST_OFF +
                        (((n0 + ntp * 16 + lq) * WST_STRIDE) + k0 + hi8) * 2);
                mma_f16(acc[0][2 * ntp],     a[0], bf[0], bf[2]);
                mma_f16(acc[0][2 * ntp + 1], a[0], bf[1], bf[3]);
                mma_f16(acc[1][2 * ntp],     a[1], bf[0], bf[2]);
                mma_f16(acc[1][2 * ntp + 1], a[1], bf[1], bf[3]);
            }
        }

        __half2* qkv2 = (__half2*)(smc + QKV_OFF);
        #pragma unroll
        for (int mt = 0; mt < 2; mt++)
            #pragma unroll
            for (int nt = 0; nt < 4; nt++) {
                int col0 = n0 + nt * 8 + 2 * tg;
                float b0 = qkv_b[p * 128 + col0];
                float b1 = qkv_b[p * 128 + col0 + 1];
                int r0 = m0 + mt * 16 + g, r1 = r0 + 8;
                int cofs = (p * 128 + col0) >> 1;
                qkv2[(r0 * QKV_STRIDE) / 2 + cofs] =
                    __floats2half2_rn(acc[mt][nt][0] + b0, acc[mt][nt][1] + b1);
                qkv2[(r1 * QKV_STRIDE) / 2 + cofs] =
                    __floats2half2_rn(acc[mt][nt][2] + b0, acc[mt][nt][3] + b1);
            }
        __syncthreads();
    }

    // stage proj weights now (Wst free; overlaps with attention below)
    stage_weights(smc, proj_w, warp, lane);

    // ---- Phase 3: attention, 2 warps/head; P stays in registers ----
    {
        const int h = warp >> 1, hw = warp & 1;
        const int rbase = hw * 32;
        const int qcol = h * 96, kcol = qcol + 32, vcol = qcol + 64;

        float S[2][8][4];
        #pragma unroll
        for (int mt = 0; mt < 2; mt++)
            #pragma unroll
            for (int nt = 0; nt < 8; nt++)
                #pragma unroll
                for (int e = 0; e < 4; e++) S[mt][nt][e] = 0.f;

        #pragma unroll
        for (int k0 = 0; k0 < 32; k0 += 16) {
            unsigned int a[2][4];
            #pragma unroll
            for (int mt = 0; mt < 2; mt++)
                ldsm_x4(a[mt], smb + QKV_OFF +
                        (((rbase + mt * 16 + lq) * QKV_STRIDE) + qcol + k0 + hi8) * 2);
            #pragma unroll
            for (int ntp = 0; ntp < 4; ntp++) {
                unsigned int bf[4];
                ldsm_x4(bf, smb + QKV_OFF +
                        (((ntp * 16 + lq) * QKV_STRIDE) + kcol + k0 + hi8) * 2);
                mma_f16(S[0][2 * ntp],     a[0], bf[0], bf[2]);
                mma_f16(S[0][2 * ntp + 1], a[0], bf[1], bf[3]);
                mma_f16(S[1][2 * ntp],     a[1], bf[0], bf[2]);
                mma_f16(S[1][2 * ntp + 1], a[1], bf[1], bf[3]);
            }
        }

        // scale + rel-pos bias, row max (rows g, g+8 per mt)
        float mx[4] = {-1e30f, -1e30f, -1e30f, -1e30f};
        #pragma unroll
        for (int mt = 0; mt < 2; mt++)
            #pragma unroll
            for (int nt = 0; nt < 8; nt++)
                #pragma unroll
                for (int e = 0; e < 4; e++) {
                    int row = rbase + mt * 16 + g + ((e >> 1) << 3);
                    int col = nt * 8 + 2 * tg + (e & 1);
                    int qi = row >> 3, qj = row & 7, ki = col >> 3, kj = col & 7;
                    int bidx = (qi - ki + 7) * 15 + (qj - kj + 7);
                    float sv = S[mt][nt][e] * SCALE_F + rpb[bidx * 4 + h];
                    S[mt][nt][e] = sv;
                    int slot = mt * 2 + (e >> 1);
                    mx[slot] = fmaxf(mx[slot], sv);
                }
        #pragma unroll
        for (int s4 = 0; s4 < 4; s4++) {
            mx[s4] = fmaxf(mx[s4], __shfl_xor_sync(0xffffffffu, mx[s4], 1));
            mx[s4] = fmaxf(mx[s4], __shfl_xor_sync(0xffffffffu, mx[s4], 2));
        }
        float sum[4] = {0.f, 0.f, 0.f, 0.f};
        #pragma unroll
        for (int mt = 0; mt < 2; mt++)
            #pragma unroll
            for (int nt = 0; nt < 8; nt++)
                #pragma unroll
                for (int e = 0; e < 4; e++) {
                    int slot = mt * 2 + (e >> 1);
                    float ev = __expf(S[mt][nt][e] - mx[slot]);
                    S[mt][nt][e] = ev;
                    sum[slot] += ev;
                }
        #pragma unroll
        for (int s4 = 0; s4 < 4; s4++) {
            sum[s4] += __shfl_xor_sync(0xffffffffu, sum[s4], 1);
            sum[s4] += __shfl_xor_sync(0xffffffffu, sum[s4], 2);
        }
        float inv[4];
        #pragma unroll
        for (int s4 = 0; s4 < 4; s4++) inv[s4] = 1.f / sum[s4];

        // pack P (unnormalized) directly into PV A-fragments: S-tile pair
        // (nt=2kp, 2kp+1) == A m16k16 fragment for kstep kp.
        unsigned int aP[2][4][4];
        #pragma unroll
        for (int mt = 0; mt < 2; mt++)
            #pragma unroll
            for (int kp = 0; kp < 4; kp++) {
                aP[mt][kp][0] = pack2(S[mt][2 * kp][0],     S[mt][2 * kp][1]);
                aP[mt][kp][1] = pack2(S[mt][2 * kp][2],     S[mt][2 * kp][3]);
                aP[mt][kp][2] = pack2(S[mt][2 * kp + 1][0], S[mt][2 * kp + 1][1]);
                aP[mt][kp][3] = pack2(S[mt][2 * kp + 1][2], S[mt][2 * kp + 1][3]);
            }

        // O = P.V : M=32, N=32, K=64. V via ldmatrix.x4.trans from [token][d].
        float O[2][4][4];
        #pragma unroll
        for (int mt = 0; mt < 2; mt++)
            #pragma unroll
            for (int nt = 0; nt < 4; nt++)
                #pragma unroll
                for (int e = 0; e < 4; e++) O[mt][nt][e] = 0.f;

        #pragma unroll
        for (int kp = 0; kp < 4; kp++) {
            #pragma unroll
            for (int vp = 0; vp < 2; vp++) {
                unsigned int bf[4];
                ldsm_x4t(bf, smb + QKV_OFF +
                         (((kp * 16 + lq) * QKV_STRIDE) + vcol + vp * 16 + hi8) * 2);
                mma_f16(O[0][2 * vp],     aP[0][kp], bf[0], bf[1]);
                mma_f16(O[0][2 * vp + 1], aP[0][kp], bf[2], bf[3]);
                mma_f16(O[1][2 * vp],     aP[1][kp], bf[0], bf[1]);
                mma_f16(O[1][2 * vp + 1], aP[1][kp], bf[2], bf[3]);
            }
        }

        // normalize, write merged-head Oa fp16 token-major (overlays Xst)
        __half2* oa2 = (__half2*)(smc + XST_OFF);
        #pragma unroll
        for (int mt = 0; mt < 2; mt++)
            #pragma unroll
            for (int nt = 0; nt < 4; nt++) {
                int col0 = h * 32 + nt * 8 + 2 * tg;
                int r0 = rbase + mt * 16 + g, r1 = r0 + 8;
                int s0 = mt * 2, s1 = mt * 2 + 1;
                oa2[(r0 * OA_STRIDE + col0) / 2] = __floats2half2_rn(
                    O[mt][nt][0] * inv[s0], O[mt][nt][1] * inv[s0]);
                oa2[(r1 * OA_STRIDE + col0) / 2] = __floats2half2_rn(
                    O[mt][nt][2] * inv[s1], O[mt][nt][3] * inv[s1]);
            }
    }
    __syncthreads();   // Oa + proj weights visible

    // ---- Phase 4: proj GEMM [64x128]x[128x128]^T ----
    {
        float acc[2][4][4];
        #pragma unroll
        for (int mt = 0; mt < 2; mt++)
            #pragma unroll
            for (int nt = 0; nt < 4; nt++)
                #pragma unroll
                for (int e = 0; e < 4; e++) acc[mt][nt][e] = 0.f;

        #pragma unroll 4
        for (int k0 = 0; k0 < 128; k0 += 16) {
            unsigned int a[2][4];
            #pragma unroll
            for (int mt = 0; mt < 2; mt++)
                ldsm_x4(a[mt], smb + XST_OFF +
                        (((m0 + mt * 16 + lq) * OA_STRIDE) + k0 + hi8) * 2);
            #pragma unroll
            for (int ntp = 0; ntp < 2; ntp++) {
                unsigned int bf[4];
                ldsm_x4(bf, smb + WST_OFF +
                        (((n0 + ntp * 16 + lq) * WST_STRIDE) + k0 + hi8) * 2);
                mma_f16(acc[0][2 * ntp],     a[0], bf[0], bf[2]);
                mma_f16(acc[0][2 * ntp + 1], a[0], bf[1], bf[3]);
                mma_f16(acc[1][2 * ntp],     a[1], bf[0], bf[2]);
                mma_f16(acc[1][2 * ntp + 1], a[1], bf[1], bf[3]);
            }
        }

        float* Pout = (float*)(smc + POUT_OFF);
        #pragma unroll
        for (int mt = 0; mt < 2; mt++)
            #pragma unroll
            for (int nt = 0; nt < 4; nt++) {
                int col0 = n0 + nt * 8 + 2 * tg;
                float b0 = proj_b[col0], b1 = proj_b[col0 + 1];
                int r0 = m0 + mt * 16 + g, r1 = r0 + 8;
                *(float2*)&Pout[r0 * POUT_STRIDE + col0] =
                    make_float2(acc[mt][nt][0] + b0, acc[mt][nt][1] + b1);
                *(float2*)&Pout[r1 * POUT_STRIDE + col0] =
                    make_float2(acc[mt][nt][2] + b0, acc[mt][nt][3] + b1);
            }
    }
    __syncthreads();

    // ---- Phase 5: scatter (vectorized) with reverse shift ----
    {
        const float* Pout = (const float*)(smc + POUT_OFF);
        #pragma unroll
        for (int it = 0; it < 8; it++) {
            int idx = tid + it * 256;
            int c = idx & 127, rh = (idx >> 7) & 15;
            int wv = rh >> 1, hf = rh & 1;
            int s0 = wv * 8 + hf * 4;
            float4 t;
            t.x = Pout[(s0 + 0) * POUT_STRIDE + c];
            t.y = Pout[(s0 + 1) * POUT_STRIDE + c];
            t.z = Pout[(s0 + 2) * POUT_STRIDE + c];
            t.w = Pout[(s0 + 3) * POUT_STRIDE + c];
            int hg = (h0 + wv + 60) & 63;
            int wg = (w0 + hf * 4 + 60) & 63;
            *(float4*)&out[bbase + c * 102400 + hg * 64 + wg] = t;
        }
    }
}

extern "C" void kernel_launch(void* const* d_in, const int* in_sizes, int n_in,
                              void* d_out, int out_size)
{
    const float* x      = (const float*)d_in[0];
    const float* qkv_w  = (const float*)d_in[1];
    const float* qkv_b  = (const float*)d_in[2];
    const float* proj_w = (const float*)d_in[3];
    const float* proj_b = (const float*)d_in[4];
    const float* rpb    = (const float*)d_in[5];
    float* out = (float*)d_out;

    cudaFuncSetAttribute(win_attn_kernel,
                         cudaFuncAttributeMaxDynamicSharedMemorySize, SMEM_BYTES);
    win_attn_kernel<<<NWIN, 256, SMEM_BYTES>>>(x, qkv_w, qkv_b, proj_w, proj_b, rpb, out);
}